// round 2
// baseline (speedup 1.0000x reference)
#include <cuda_runtime.h>
#include <cstddef>

#define N_USERS 200000
#define N_ITEMS 100000
#define N_NODES 300000
#define DIM     64
#define N_EDGES 1200000

#define SCAN_BLK 1024
#define NB_SCAN  ((N_NODES + SCAN_BLK - 1) / SCAN_BLK)   // 293
static_assert(NB_SCAN <= 512, "scan2 single-block limit");

// CSR scratch (static device arrays; ~12 MB total)
__device__ int   g_deg[N_NODES];
__device__ int   g_off[N_NODES + 1];
__device__ int   g_bsum[NB_SCAN];
__device__ int   g_bcol[N_EDGES];
__device__ float g_bval[N_EDGES];
__device__ int   g_identity;

__device__ __forceinline__ float sigf(float x) {
    return 1.0f / (1.0f + __expf(-x));
}

// ---------------------------------------------------------------------------
// Init: zero degree counts; last block checks filt == I
// ---------------------------------------------------------------------------
__global__ void k_init(const float* __restrict__ filt) {
    if (blockIdx.x == gridDim.x - 1) {
        __shared__ int ok;
        if (threadIdx.x == 0) ok = 1;
        __syncthreads();
        for (int i = threadIdx.x; i < DIM * DIM; i += blockDim.x) {
            int r = i >> 6, c = i & 63;
            float expect = (r == c) ? 1.0f : 0.0f;
            if (filt[i] != expect) atomicAnd(&ok, 0);
        }
        __syncthreads();
        if (threadIdx.x == 0) g_identity = ok;
        return;
    }
    unsigned idx = blockIdx.x * blockDim.x + threadIdx.x;
    if (idx < (unsigned)(N_NODES / 4)) {
        reinterpret_cast<int4*>(g_deg)[idx] = make_int4(0, 0, 0, 0);
    }
}

// ---------------------------------------------------------------------------
// Histogram of destination rows
// ---------------------------------------------------------------------------
__global__ void k_hist(const int* __restrict__ rows) {
    unsigned e = blockIdx.x * blockDim.x + threadIdx.x;
    if (e < (unsigned)N_EDGES) {
        atomicAdd(&g_deg[__ldg(rows + e)], 1);
    }
}

// ---------------------------------------------------------------------------
// Scan pass 1: per-block exclusive scan of deg -> off, block totals -> bsum
// ---------------------------------------------------------------------------
__global__ void k_scan1() {
    __shared__ int wsum[32];
    int i = blockIdx.x * SCAN_BLK + threadIdx.x;
    int v = (i < N_NODES) ? g_deg[i] : 0;
    int lane = threadIdx.x & 31, wid = threadIdx.x >> 5;

    int x = v;                                   // warp inclusive scan
    #pragma unroll
    for (int d = 1; d < 32; d <<= 1) {
        int y = __shfl_up_sync(0xffffffffu, x, d);
        if (lane >= d) x += y;
    }
    if (lane == 31) wsum[wid] = x;
    __syncthreads();
    if (wid == 0) {                              // scan the 32 warp totals
        int s = wsum[lane];
        #pragma unroll
        for (int d = 1; d < 32; d <<= 1) {
            int y = __shfl_up_sync(0xffffffffu, s, d);
            if (lane >= d) s += y;
        }
        wsum[lane] = s;
    }
    __syncthreads();
    int warpoff = (wid == 0) ? 0 : wsum[wid - 1];
    if (i < N_NODES) g_off[i] = warpoff + x - v; // exclusive within block
    if (threadIdx.x == SCAN_BLK - 1) g_bsum[blockIdx.x] = warpoff + x;
}

// ---------------------------------------------------------------------------
// Scan pass 2: single-block exclusive scan of block sums
// ---------------------------------------------------------------------------
__global__ void k_scan2() {
    __shared__ int sh[512];
    int tid = threadIdx.x;
    int v = (tid < NB_SCAN) ? g_bsum[tid] : 0;
    sh[tid] = v;
    __syncthreads();
    #pragma unroll
    for (int d = 1; d < 512; d <<= 1) {
        int t = (tid >= d) ? sh[tid - d] : 0;
        __syncthreads();
        sh[tid] += t;
        __syncthreads();
    }
    if (tid < NB_SCAN) g_bsum[tid] = sh[tid] - v;  // exclusive
}

// ---------------------------------------------------------------------------
// Scan pass 3: add block prefixes; set off[N] = N_EDGES
// ---------------------------------------------------------------------------
__global__ void k_scan3() {
    unsigned i = blockIdx.x * blockDim.x + threadIdx.x;
    if (i < (unsigned)N_NODES) g_off[i] += g_bsum[i >> 10];
    if (i == (unsigned)N_NODES) g_off[N_NODES] = N_EDGES;
}

// ---------------------------------------------------------------------------
// Scatter edges into row buckets (reuses g_deg as a down-counter)
// ---------------------------------------------------------------------------
__global__ void k_scatter(const int*   __restrict__ rows,
                          const int*   __restrict__ cols,
                          const float* __restrict__ vals) {
    unsigned e = blockIdx.x * blockDim.x + threadIdx.x;
    if (e >= (unsigned)N_EDGES) return;
    int r = __ldg(rows + e);
    int pos = g_off[r] + atomicSub(&g_deg[r], 1) - 1;
    g_bcol[pos] = __ldg(cols + e);
    g_bval[pos] = __ldg(vals + e);
}

// ---------------------------------------------------------------------------
// Fused consume + epilogue: one warp per node.
// Lane l owns cols [2l, 2l+1] of the 64-dim row (float2).
// ---------------------------------------------------------------------------
__global__ void k_consume(const float2* __restrict__ ue2,
                          const float2* __restrict__ ie2,
                          const float*  __restrict__ filt,
                          float2*       __restrict__ out2) {
    unsigned gwarp = (blockIdx.x * blockDim.x + threadIdx.x) >> 5;
    int lane = threadIdx.x & 31;
    int wslot = (threadIdx.x >> 5);              // warp within block (0..7)
    if (gwarp >= (unsigned)N_NODES) return;
    int n = (int)gwarp;

    int beg = __ldg(&g_off[n]);
    int end = __ldg(&g_off[n + 1]);

    float2 acc = make_float2(0.f, 0.f);
    int cnt = end - beg;
    for (int base = 0; base < cnt; base += 32) {
        int m = min(32, cnt - base);
        int   mycol = 0;
        float myval = 0.f;
        if (lane < m) {
            mycol = g_bcol[beg + base + lane];
            myval = g_bval[beg + base + lane];
        }
        for (int j = 0; j < m; ++j) {
            int   col = __shfl_sync(0xffffffffu, mycol, j);
            float v   = __shfl_sync(0xffffffffu, myval, j);
            const float2* src = (col < N_USERS)
                ? (ue2 + (size_t)col * 32)
                : (ie2 + (size_t)(col - N_USERS) * 32);
            float2 x = __ldg(src + lane);
            acc.x += v * x.x;
            acc.y += v * x.y;
        }
    }

    // own embedding row
    const float2* esrc = (n < N_USERS)
        ? (ue2 + (size_t)n * 32)
        : (ie2 + (size_t)(n - N_USERS) * 32);
    float2 e = __ldg(esrc + lane);

    // out row = 128 floats = 64 float2; first 32 float2 = emb, next 32 = h
    out2[(size_t)n * 64 + lane] = e;

    float2 t;
    t.x = 2.0f * e.x - acc.x;
    t.y = 2.0f * e.y - acc.y;

    if (g_identity) {
        out2[(size_t)n * 64 + 32 + lane] = make_float2(sigf(t.x), sigf(t.y));
    } else {
        // generic fallback: t @ filt staged through shared memory
        __shared__ float ts[8][DIM];
        ts[wslot][2 * lane]     = t.x;
        ts[wslot][2 * lane + 1] = t.y;
        __syncwarp();
        float s0 = 0.f, s1 = 0.f;
        int c0 = 2 * lane, c1 = 2 * lane + 1;
        #pragma unroll 8
        for (int k = 0; k < DIM; k++) {
            float tk = ts[wslot][k];
            s0 += tk * __ldg(filt + (size_t)k * DIM + c0);
            s1 += tk * __ldg(filt + (size_t)k * DIM + c1);
        }
        out2[(size_t)n * 64 + 32 + lane] = make_float2(sigf(s0), sigf(s1));
    }
}

// ---------------------------------------------------------------------------
// Launch
// ---------------------------------------------------------------------------
extern "C" void kernel_launch(void* const* d_in, const int* in_sizes, int n_in,
                              void* d_out, int out_size) {
    const int*   rows = (const int*)  d_in[0];
    const int*   cols = (const int*)  d_in[1];
    const float* vals = (const float*)d_in[2];
    const float* ue   = (const float*)d_in[3];
    const float* ie   = (const float*)d_in[4];
    const float* filt = (const float*)d_in[5];
    float*       out  = (float*)d_out;

    const int zero_blocks = (N_NODES / 4 + 255) / 256;           // 293
    k_init<<<zero_blocks + 1, 256>>>(filt);

    const int edge_blocks = (N_EDGES + 255) / 256;               // 4688
    k_hist<<<edge_blocks, 256>>>(rows);

    k_scan1<<<NB_SCAN, SCAN_BLK>>>();
    k_scan2<<<1, 512>>>();
    k_scan3<<<(N_NODES + 256) / 256, 256>>>();

    k_scatter<<<edge_blocks, 256>>>(rows, cols, vals);

    const int consume_blocks = (N_NODES * 32 + 255) / 256;       // 37500
    k_consume<<<consume_blocks, 256>>>(
        (const float2*)ue, (const float2*)ie, filt, (float2*)out);
}

// round 3
// speedup vs baseline: 1.0048x; 1.0048x over previous
#include <cuda_runtime.h>
#include <cstddef>

#define N_USERS 200000
#define N_ITEMS 100000
#define N_NODES 300000
#define DIM     64
#define N_EDGES 1200000

// 1 if filt == eye(64), else 0. Recomputed every launch (deterministic).
__device__ int g_identity;

__device__ __forceinline__ float sigf(float x) {
    return 1.0f / (1.0f + __expf(-x));
}

// ---------------------------------------------------------------------------
// Seed: out[n, 0:64] = emb[n];  out[n, 64:128] = 2*emb[n]  (the accumulator
// seed for h = 2e - sum(val*emb[col])). Also: block 0 checks filt == I.
// 16 threads per node, float4 lanes.
// ---------------------------------------------------------------------------
__global__ void seed_kernel(const float4* __restrict__ ue4,
                            const float4* __restrict__ ie4,
                            const float*  __restrict__ filt,
                            float4*       __restrict__ out4) {
    if (blockIdx.x == gridDim.x - 1) {
        // filt identity check (one spare block)
        __shared__ int ok;
        if (threadIdx.x == 0) ok = 1;
        __syncthreads();
        for (int i = threadIdx.x; i < DIM * DIM; i += blockDim.x) {
            int r = i >> 6, c = i & 63;
            float expect = (r == c) ? 1.0f : 0.0f;
            if (filt[i] != expect) atomicAnd(&ok, 0);
        }
        __syncthreads();
        if (threadIdx.x == 0) g_identity = ok;
        return;
    }
    unsigned idx = blockIdx.x * blockDim.x + threadIdx.x;
    unsigned n = idx >> 4;
    unsigned c = idx & 15u;
    if (n >= (unsigned)N_NODES) return;

    float4 e = (n < N_USERS) ? __ldg(ue4 + (size_t)n * 16 + c)
                             : __ldg(ie4 + (size_t)(n - N_USERS) * 16 + c);
    out4[(size_t)n * 32 + c] = e;
    float4 e2 = make_float4(2.f * e.x, 2.f * e.y, 2.f * e.z, 2.f * e.w);
    out4[(size_t)n * 32 + 16 + c] = e2;
}

// ---------------------------------------------------------------------------
// Edge scatter: out_h[row] -= val * emb[col]  (vector L2 reduction, in place)
// 16 threads per edge, one float4 (16B) per thread.
// ---------------------------------------------------------------------------
__global__ void edge_kernel(const int*    __restrict__ rows,
                            const int*    __restrict__ cols,
                            const float*  __restrict__ vals,
                            const float4* __restrict__ ue4,
                            const float4* __restrict__ ie4,
                            float4*       __restrict__ out4) {
    unsigned idx = blockIdx.x * blockDim.x + threadIdx.x;
    if (idx >= (unsigned)N_EDGES * 16u) return;
    unsigned e = idx >> 4;
    unsigned c = idx & 15u;

    int   col = __ldg(cols + e);
    int   row = __ldg(rows + e);
    float v   = -__ldg(vals + e);     // negated: accumulator computes 2e - agg

    float4 x = (col < N_USERS)
        ? __ldg(ue4 + (size_t)col * 16 + c)
        : __ldg(ie4 + (size_t)(col - N_USERS) * 16 + c);

    x.x *= v; x.y *= v; x.z *= v; x.w *= v;

    float4* dst = out4 + (size_t)row * 32 + 16 + c;
    asm volatile("red.global.add.v4.f32 [%0], {%1, %2, %3, %4};"
                 :: "l"(dst), "f"(x.x), "f"(x.y), "f"(x.z), "f"(x.w)
                 : "memory");
}

// ---------------------------------------------------------------------------
// Epilogue: h-half currently holds t = 2e - agg. Apply sigmoid in place
// (identity filt fast path) or t @ filt via smem fallback.
// blockDim must be 256 (16 nodes/block) for the fallback staging.
// ---------------------------------------------------------------------------
__global__ void epi_kernel(const float* __restrict__ filt,
                           float4*      __restrict__ out4) {
    unsigned idx = blockIdx.x * blockDim.x + threadIdx.x;
    unsigned n = idx >> 4;
    unsigned c = idx & 15u;
    bool active = (n < (unsigned)N_NODES);

    float4 t = make_float4(0.f, 0.f, 0.f, 0.f);
    if (active) t = out4[(size_t)n * 32 + 16 + c];

    if (g_identity) {
        if (active) {
            float4 h;
            h.x = sigf(t.x); h.y = sigf(t.y); h.z = sigf(t.z); h.w = sigf(t.w);
            out4[(size_t)n * 32 + 16 + c] = h;
        }
    } else {
        __shared__ float ts[16][DIM];
        unsigned ln = threadIdx.x >> 4;
        ts[ln][c * 4 + 0] = t.x;
        ts[ln][c * 4 + 1] = t.y;
        ts[ln][c * 4 + 2] = t.z;
        ts[ln][c * 4 + 3] = t.w;
        __syncthreads();
        if (active) {
            const float* trow = ts[ln];
            float s[4] = {0.f, 0.f, 0.f, 0.f};
            #pragma unroll 8
            for (int k = 0; k < DIM; k++) {
                float tk = trow[k];
                const float* frow = filt + (size_t)k * DIM + c * 4;
                s[0] += tk * frow[0];
                s[1] += tk * frow[1];
                s[2] += tk * frow[2];
                s[3] += tk * frow[3];
            }
            float4 h;
            h.x = sigf(s[0]); h.y = sigf(s[1]); h.z = sigf(s[2]); h.w = sigf(s[3]);
            out4[(size_t)n * 32 + 16 + c] = h;
        }
    }
}

// ---------------------------------------------------------------------------
// Launch
// ---------------------------------------------------------------------------
extern "C" void kernel_launch(void* const* d_in, const int* in_sizes, int n_in,
                              void* d_out, int out_size) {
    const int*   rows = (const int*)  d_in[0];
    const int*   cols = (const int*)  d_in[1];
    const float* vals = (const float*)d_in[2];
    const float* ue   = (const float*)d_in[3];
    const float* ie   = (const float*)d_in[4];
    const float* filt = (const float*)d_in[5];
    float4*      out4 = (float4*)d_out;

    const unsigned seed_threads = (unsigned)N_NODES * 16u;       // 4.8M
    const unsigned seed_blocks  = (seed_threads + 255) / 256;
    seed_kernel<<<seed_blocks + 1, 256>>>(
        (const float4*)ue, (const float4*)ie, filt, out4);

    const unsigned edge_threads = (unsigned)N_EDGES * 16u;       // 19.2M
    edge_kernel<<<(edge_threads + 255) / 256, 256>>>(
        rows, cols, vals, (const float4*)ue, (const float4*)ie, out4);

    const unsigned epi_threads = (unsigned)N_NODES * 16u;        // 4.8M
    epi_kernel<<<(epi_threads + 255) / 256, 256>>>(filt, out4);
}

// round 4
// speedup vs baseline: 1.5174x; 1.5101x over previous
#include <cuda_runtime.h>
#include <cuda_bf16.h>
#include <cstddef>

#define N_USERS 200000
#define N_ITEMS 100000
#define N_NODES 300000
#define DIM     64
#define N_EDGES 1200000

// bf16 copy of emb and bf16 accumulator (128 B per node each; 38.4 MB each)
__device__ uint4 g_embh[(size_t)N_NODES * 8];
__device__ uint4 g_acc [(size_t)N_NODES * 8];
__device__ int   g_identity;

__device__ __forceinline__ float sigf(float x) {
    return 1.0f / (1.0f + __expf(-x));
}

__device__ __forceinline__ unsigned pack_bf2(float a, float b) {
    __nv_bfloat162 p = __floats2bfloat162_rn(a, b);
    return reinterpret_cast<unsigned&>(p);
}
__device__ __forceinline__ float2 unpack_bf2(unsigned u) {
    __nv_bfloat162 p = reinterpret_cast<__nv_bfloat162&>(u);
    return __bfloat1622float2(p);
}
__device__ __forceinline__ unsigned mul_bf2(unsigned a, unsigned b) {
    __nv_bfloat162 pa = reinterpret_cast<__nv_bfloat162&>(a);
    __nv_bfloat162 pb = reinterpret_cast<__nv_bfloat162&>(b);
    __nv_bfloat162 r = __hmul2(pa, pb);
    return reinterpret_cast<unsigned&>(r);
}

// ---------------------------------------------------------------------------
// Seed: out[n,0:64] = emb (f32); g_embh[n] = bf16(emb); g_acc[n] = bf16(2*emb).
// 16 threads/node (float4 lanes). Last block checks filt == I.
// ---------------------------------------------------------------------------
__global__ void seed_kernel(const float4* __restrict__ ue4,
                            const float4* __restrict__ ie4,
                            const float*  __restrict__ filt,
                            float4*       __restrict__ out4) {
    if (blockIdx.x == gridDim.x - 1) {
        __shared__ int ok;
        if (threadIdx.x == 0) ok = 1;
        __syncthreads();
        for (int i = threadIdx.x; i < DIM * DIM; i += blockDim.x) {
            int r = i >> 6, c = i & 63;
            float expect = (r == c) ? 1.0f : 0.0f;
            if (filt[i] != expect) atomicAnd(&ok, 0);
        }
        __syncthreads();
        if (threadIdx.x == 0) g_identity = ok;
        return;
    }
    unsigned idx = blockIdx.x * blockDim.x + threadIdx.x;
    unsigned n = idx >> 4;
    unsigned c = idx & 15u;
    if (n >= (unsigned)N_NODES) return;

    float4 e = (n < N_USERS) ? __ldg(ue4 + (size_t)n * 16 + c)
                             : __ldg(ie4 + (size_t)(n - N_USERS) * 16 + c);
    out4[(size_t)n * 32 + c] = e;

    uint2 eh;
    eh.x = pack_bf2(e.x, e.y);
    eh.y = pack_bf2(e.z, e.w);
    reinterpret_cast<uint2*>(g_embh)[(size_t)n * 16 + c] = eh;

    uint2 a2;
    a2.x = pack_bf2(2.f * e.x, 2.f * e.y);
    a2.y = pack_bf2(2.f * e.z, 2.f * e.w);
    reinterpret_cast<uint2*>(g_acc)[(size_t)n * 16 + c] = a2;
}

// ---------------------------------------------------------------------------
// Edge scatter: acc[row] -= val * embh[col]   (bf16x2 vector L2 reduction)
// 8 threads/edge; each thread handles 8 bf16 values (16 B).
// ---------------------------------------------------------------------------
__global__ void edge_kernel(const int*   __restrict__ rows,
                            const int*   __restrict__ cols,
                            const float* __restrict__ vals) {
    unsigned idx = blockIdx.x * blockDim.x + threadIdx.x;
    if (idx >= (unsigned)N_EDGES * 8u) return;
    unsigned e = idx >> 3;
    unsigned c = idx & 7u;

    int   col = __ldg(cols + e);
    int   row = __ldg(rows + e);
    float v   = -__ldg(vals + e);          // negated: acc computes 2e - agg
    unsigned vv = pack_bf2(v, v);

    uint4 x = __ldg(&g_embh[(size_t)col * 8 + c]);
    x.x = mul_bf2(x.x, vv);
    x.y = mul_bf2(x.y, vv);
    x.z = mul_bf2(x.z, vv);
    x.w = mul_bf2(x.w, vv);

    uint4* dst = &g_acc[(size_t)row * 8 + c];
    asm volatile("red.global.add.noftz.v4.bf16x2 [%0], {%1, %2, %3, %4};"
                 :: "l"(dst), "r"(x.x), "r"(x.y), "r"(x.z), "r"(x.w)
                 : "memory");
}

// ---------------------------------------------------------------------------
// Epilogue: acc holds t = 2e - agg (bf16). out[n,64:128] = sigmoid(t) or
// sigmoid(t @ filt) fallback. 8 threads/node; blockDim 256 (32 nodes/block).
// ---------------------------------------------------------------------------
__global__ void epi_kernel(const float* __restrict__ filt,
                           float4*      __restrict__ out4) {
    unsigned idx = blockIdx.x * blockDim.x + threadIdx.x;
    unsigned n = idx >> 3;
    unsigned c = idx & 7u;
    bool active = (n < (unsigned)N_NODES);

    uint4 a = make_uint4(0, 0, 0, 0);
    if (active) a = g_acc[(size_t)n * 8 + c];
    float2 t0 = unpack_bf2(a.x);
    float2 t1 = unpack_bf2(a.y);
    float2 t2 = unpack_bf2(a.z);
    float2 t3 = unpack_bf2(a.w);

    if (g_identity) {
        if (active) {
            float4 h0 = make_float4(sigf(t0.x), sigf(t0.y), sigf(t1.x), sigf(t1.y));
            float4 h1 = make_float4(sigf(t2.x), sigf(t2.y), sigf(t3.x), sigf(t3.y));
            out4[(size_t)n * 32 + 16 + c * 2]     = h0;
            out4[(size_t)n * 32 + 16 + c * 2 + 1] = h1;
        }
    } else {
        __shared__ float ts[32][DIM];
        unsigned ln = threadIdx.x >> 3;          // node slot within block
        float* tr = ts[ln] + c * 8;
        tr[0] = t0.x; tr[1] = t0.y; tr[2] = t1.x; tr[3] = t1.y;
        tr[4] = t2.x; tr[5] = t2.y; tr[6] = t3.x; tr[7] = t3.y;
        __syncthreads();
        if (active) {
            const float* trow = ts[ln];
            float s[8] = {0.f};
            #pragma unroll 8
            for (int k = 0; k < DIM; k++) {
                float tk = trow[k];
                const float* frow = filt + (size_t)k * DIM + c * 8;
                #pragma unroll
                for (int j = 0; j < 8; j++) s[j] += tk * frow[j];
            }
            float4 h0 = make_float4(sigf(s[0]), sigf(s[1]), sigf(s[2]), sigf(s[3]));
            float4 h1 = make_float4(sigf(s[4]), sigf(s[5]), sigf(s[6]), sigf(s[7]));
            out4[(size_t)n * 32 + 16 + c * 2]     = h0;
            out4[(size_t)n * 32 + 16 + c * 2 + 1] = h1;
        }
    }
}

// ---------------------------------------------------------------------------
// Launch
// ---------------------------------------------------------------------------
extern "C" void kernel_launch(void* const* d_in, const int* in_sizes, int n_in,
                              void* d_out, int out_size) {
    const int*   rows = (const int*)  d_in[0];
    const int*   cols = (const int*)  d_in[1];
    const float* vals = (const float*)d_in[2];
    const float* ue   = (const float*)d_in[3];
    const float* ie   = (const float*)d_in[4];
    const float* filt = (const float*)d_in[5];
    float4*      out4 = (float4*)d_out;

    const unsigned seed_threads = (unsigned)N_NODES * 16u;       // 4.8M
    const unsigned seed_blocks  = (seed_threads + 255) / 256;
    seed_kernel<<<seed_blocks + 1, 256>>>(
        (const float4*)ue, (const float4*)ie, filt, out4);

    const unsigned edge_threads = (unsigned)N_EDGES * 8u;        // 9.6M
    edge_kernel<<<(edge_threads + 255) / 256, 256>>>(rows, cols, vals);

    const unsigned epi_threads = (unsigned)N_NODES * 8u;         // 2.4M
    epi_kernel<<<(epi_threads + 255) / 256, 256>>>(filt, out4);
}